// round 4
// baseline (speedup 1.0000x reference)
#include <cuda_runtime.h>
#include <cstdint>

// VQ nearest-codebook search:
//   inputs  [16, 64, 64, 64]  NCHW fp32  (C = D = 64)
//   codebook[1024, 64]        fp32
//   out[65536] = argmin_k || x_n - e_k ||^2, EMITTED AS float32
//   (harness __output__ dtype hypothesis: float32; int32 written previously
//    reads as denormals ~ 0 -> rel_err exactly 1.0, matching R2/R3)
// Order-preserving reduction: argmin_k ( 0.5*||e_k||^2 - x_n . e_k )

#define NUM_CODES 1024
#define DIM       64
#define TK        64           // codes per smem tile
#define THREADS   64           // threads per block (one row per thread)
#define N_ROWS    65536
#define HW        4096         // 64*64 spatial

__device__ float g_h[NUM_CODES];   // h[k] = +0.5 * ||e_k||^2

// ---------------------------------------------------------------------------
// Kernel 1: precompute h[k]
// ---------------------------------------------------------------------------
__global__ void vq_cnorm_kernel(const float* __restrict__ cb) {
    int k = blockIdx.x * blockDim.x + threadIdx.x;
    if (k < NUM_CODES) {
        const float4* row = (const float4*)(cb + (size_t)k * DIM);
        float s = 0.f;
#pragma unroll
        for (int i = 0; i < DIM / 4; ++i) {
            float4 v = row[i];
            s = fmaf(v.x, v.x, s);
            s = fmaf(v.y, v.y, s);
            s = fmaf(v.z, v.z, s);
            s = fmaf(v.w, v.w, s);
        }
        g_h[k] = 0.5f * s;
    }
}

// ---------------------------------------------------------------------------
// Kernel 2: main search. One thread = one row (spatial position).
// Consecutive threads = consecutive w  ->  every per-d global load coalesced.
// Codebook tile staged in smem; all lanes of a warp read the SAME code
// vector -> pure broadcast LDS.128, conflict-free.
// ---------------------------------------------------------------------------
__global__ __launch_bounds__(THREADS, 8)
void vq_search_kernel(const float* __restrict__ in,
                      const float* __restrict__ cb,
                      float* __restrict__ out) {
    __shared__ float4 sE[TK * (DIM / 4)];   // 64 codes x 64 floats = 16 KB
    __shared__ float  sH[TK];

    const int n  = blockIdx.x * THREADS + threadIdx.x;   // row id
    const int b  = n >> 12;          // batch
    const int hw = n & (HW - 1);     // spatial offset

    // This row's 64 channel values (stride HW in NCHW), kept in registers.
    const float* xin = in + ((size_t)b * DIM * HW) + hw;
    float x[DIM];
#pragma unroll
    for (int d = 0; d < DIM; ++d)
        x[d] = xin[(size_t)d * HW];

    float best = 3.402823466e38f;
    int   bidx = 0;

    const float4* cb4 = (const float4*)cb;

    for (int t = 0; t < NUM_CODES / TK; ++t) {
        __syncthreads();
        // Cooperative tile load: TK*16 = 1024 float4, 16 per thread.
#pragma unroll
        for (int i = 0; i < TK * (DIM / 4) / THREADS; ++i) {
            sE[i * THREADS + threadIdx.x] =
                cb4[(size_t)t * TK * (DIM / 4) + i * THREADS + threadIdx.x];
        }
        sH[threadIdx.x] = g_h[t * TK + threadIdx.x];
        __syncthreads();

#pragma unroll 2
        for (int kk = 0; kk < TK; ++kk) {
            const float4* e = &sE[kk * (DIM / 4)];
            float a0 = 0.f, a1 = 0.f, a2 = 0.f, a3 = 0.f;
#pragma unroll
            for (int j = 0; j < DIM / 16; ++j) {         // 4 iters x 4 float4
                float4 e0 = e[4 * j + 0];
                float4 e1 = e[4 * j + 1];
                float4 e2 = e[4 * j + 2];
                float4 e3 = e[4 * j + 3];
                const float* xp = &x[16 * j];
                a0 = fmaf(xp[ 0], e0.x, a0);
                a0 = fmaf(xp[ 1], e0.y, a0);
                a0 = fmaf(xp[ 2], e0.z, a0);
                a0 = fmaf(xp[ 3], e0.w, a0);
                a1 = fmaf(xp[ 4], e1.x, a1);
                a1 = fmaf(xp[ 5], e1.y, a1);
                a1 = fmaf(xp[ 6], e1.z, a1);
                a1 = fmaf(xp[ 7], e1.w, a1);
                a2 = fmaf(xp[ 8], e2.x, a2);
                a2 = fmaf(xp[ 9], e2.y, a2);
                a2 = fmaf(xp[10], e2.z, a2);
                a2 = fmaf(xp[11], e2.w, a2);
                a3 = fmaf(xp[12], e3.x, a3);
                a3 = fmaf(xp[13], e3.y, a3);
                a3 = fmaf(xp[14], e3.z, a3);
                a3 = fmaf(xp[15], e3.w, a3);
            }
            float dot = (a0 + a1) + (a2 + a3);
            float s   = sH[kk] - dot;      // 0.5||e||^2 - x.e  (order == dist)
            if (s < best) {                // strict < keeps first index on ties
                best = s;
                bidx = t * TK + kk;
            }
        }
    }

    out[n] = (float)bidx;    // <-- dtype experiment: emit as float32
}

// ---------------------------------------------------------------------------
// Harness entry
// ---------------------------------------------------------------------------
extern "C" void kernel_launch(void* const* d_in, const int* in_sizes, int n_in,
                              void* d_out, int out_size) {
    const float* inp = (const float*)d_in[0];
    const float* cb  = (const float*)d_in[1];
    // Defensive: identify the codebook by element count (1024*64 = 65536).
    if (in_sizes[0] == NUM_CODES * DIM && in_sizes[1] != NUM_CODES * DIM) {
        const float* tmp = inp; inp = cb; cb = tmp;
    }
    float* out = (float*)d_out;

    vq_cnorm_kernel<<<NUM_CODES / 256, 256>>>(cb);
    vq_search_kernel<<<N_ROWS / THREADS, THREADS>>>(inp, cb, out);
}

// round 5
// speedup vs baseline: 1.6131x; 1.6131x over previous
#include <cuda_runtime.h>
#include <cstdint>

// VQ nearest-codebook search (out emitted as float32 — harness dtype):
//   inputs  [16, 64, 64, 64] NCHW fp32, codebook [1024, 64] fp32
//   out[n] = argmin_k ||x_n - e_k||^2  ==  argmax_k ( x_n.e_k - 0.5||e_k||^2 )
//
// R5: register-tiled GEMM-style search.
//   block: 256 threads = 16 thread-rows (tr) x 16 thread-cols (tc)
//   M_TILE = 128 rows  (tr owns 8 rows), K_TILE = 64 codes (tc owns 4 codes)
//   16 code tiles; per-thread acc = 8 rows x 4 codes as f32x2 (rows paired).
//   smem: xT[64][128] (32KB) + eT[64][64] (16KB) = 48KB exactly.

#define NUM_CODES 1024
#define DIM       64
#define M_TILE    128
#define K_TILE    64
#define THREADS   256
#define N_ROWS    65536
#define HW        4096

__device__ float g_nh[NUM_CODES];                 // -0.5*||e_k||^2
__device__ float g_cbT[DIM][NUM_CODES];           // transposed codebook

// packed fp32x2 FMA: acc.{lo,hi} += a.{lo,hi} * b.{lo,hi}
#define FMA2(acc, a, b) \
    asm("fma.rn.f32x2 %0, %1, %2, %0;" : "+l"(acc) : "l"(a), "l"(b))
// duplicate a scalar float into both lanes of an f32x2
#define DUP2(dst, s) \
    asm("mov.b64 %0, {%1, %1};" : "=l"(dst) : "f"(s))

// ---------------------------------------------------------------------------
// Prep: h[k] and codebook transpose (one-time, tiny)
// ---------------------------------------------------------------------------
__global__ void vq_prep_kernel(const float* __restrict__ cb) {
    int k = blockIdx.x * blockDim.x + threadIdx.x;
    if (k < NUM_CODES) {
        float s = 0.f;
#pragma unroll
        for (int d = 0; d < DIM; ++d) {
            float v = cb[(size_t)k * DIM + d];
            g_cbT[d][k] = v;
            s = fmaf(v, v, s);
        }
        g_nh[k] = -0.5f * s;
    }
}

// ---------------------------------------------------------------------------
// Main search
// ---------------------------------------------------------------------------
struct Cand { float v; int i; };

__global__ __launch_bounds__(THREADS)
void vq_search_kernel(const float* __restrict__ in,
                      float* __restrict__ out) {
    __shared__ __align__(16) float xT[DIM][M_TILE];   // 32 KB
    __shared__ __align__(16) float eT[DIM][K_TILE];   // 16 KB (reused as red)

    const int tid = threadIdx.x;
    const int tr  = tid >> 4;          // 0..15  -> rows tr*8 .. tr*8+7
    const int tc  = tid & 15;          // 0..15  -> codes tc*4 .. tc*4+3
    const int r0  = tr * 8;

    // ---- load x tile: 128 consecutive rows (hw) x 64 channels ----
    // rows of this block live in one batch b (4096 % 128 == 0)
    const int rowBase = blockIdx.x * M_TILE;
    const int b   = rowBase >> 12;
    const int hw0 = rowBase & (HW - 1);
    const float* xin = in + ((size_t)b * DIM * HW) + hw0;
    // 64 d x 128 floats = 2048 float4; 8 per thread
#pragma unroll
    for (int i = 0; i < 8; ++i) {
        int idx = i * THREADS + tid;          // float4 index
        int d   = idx >> 5;                   // 32 float4 per d-row
        int m4  = idx & 31;
        ((float4*)&xT[d][0])[m4] =
            ((const float4*)(xin + (size_t)d * HW))[m4];
    }

    float best[8];
    int   bidx[8];
#pragma unroll
    for (int r = 0; r < 8; ++r) { best[r] = -3.402823466e38f; bidx[r] = 0; }

    for (int t = 0; t < NUM_CODES / K_TILE; ++t) {
        const int cBase = t * K_TILE;
        __syncthreads();   // previous iter done reading eT
        // ---- load e tile (transposed): 64 d x 64 codes = 1024 float4 ----
#pragma unroll
        for (int i = 0; i < 4; ++i) {
            int idx = i * THREADS + tid;      // float4 index
            int d   = idx >> 4;               // 16 float4 per d-row
            int j4  = idx & 15;
            ((float4*)&eT[d][0])[j4] =
                ((const float4*)&g_cbT[d][cBase])[j4];
        }
        __syncthreads();   // eT (and, at t=0, xT) ready

        // ---- accumulators: rows paired in f32x2 lanes, init = -0.5||e||^2
        const float4 nh4 = *(const float4*)&g_nh[cBase + tc * 4];
        unsigned long long h0, h1, h2, h3;
        DUP2(h0, nh4.x); DUP2(h1, nh4.y); DUP2(h2, nh4.z); DUP2(h3, nh4.w);
        unsigned long long acc[4][4];
#pragma unroll
        for (int q = 0; q < 4; ++q) {
            acc[q][0] = h0; acc[q][1] = h1; acc[q][2] = h2; acc[q][3] = h3;
        }

#pragma unroll 16
        for (int d = 0; d < DIM; ++d) {
            const ulonglong2 xa = *(const ulonglong2*)&xT[d][r0];
            const ulonglong2 xb = *(const ulonglong2*)&xT[d][r0 + 4];
            const float4     ev = *(const float4*)&eT[d][tc * 4];
            unsigned long long e0, e1, e2, e3;
            DUP2(e0, ev.x); DUP2(e1, ev.y); DUP2(e2, ev.z); DUP2(e3, ev.w);
            FMA2(acc[0][0], xa.x, e0); FMA2(acc[0][1], xa.x, e1);
            FMA2(acc[0][2], xa.x, e2); FMA2(acc[0][3], xa.x, e3);
            FMA2(acc[1][0], xa.y, e0); FMA2(acc[1][1], xa.y, e1);
            FMA2(acc[1][2], xa.y, e2); FMA2(acc[1][3], xa.y, e3);
            FMA2(acc[2][0], xb.x, e0); FMA2(acc[2][1], xb.x, e1);
            FMA2(acc[2][2], xb.x, e2); FMA2(acc[2][3], xb.x, e3);
            FMA2(acc[3][0], xb.y, e0); FMA2(acc[3][1], xb.y, e1);
            FMA2(acc[3][2], xb.y, e2); FMA2(acc[3][3], xb.y, e3);
        }

        // ---- epilogue: score = dot - 0.5||e||^2 (already folded); argmax.
        // codes visited ascending -> strict > keeps smallest index on ties.
#pragma unroll
        for (int c = 0; c < 4; ++c) {
            const int code = cBase + tc * 4 + c;
#pragma unroll
            for (int q = 0; q < 4; ++q) {
                unsigned long long a = acc[q][c];
                float vlo = __uint_as_float((unsigned)a);
                float vhi = __uint_as_float((unsigned)(a >> 32));
                int rlo = 2 * q, rhi = 2 * q + 1;
                if (vlo > best[rlo]) { best[rlo] = vlo; bidx[rlo] = code; }
                if (vhi > best[rhi]) { best[rhi] = vhi; bidx[rhi] = code; }
            }
        }
    }

    // ---- cross-thread reduction over the 16 thread-cols (alias eT) ----
    __syncthreads();
    Cand* red = (Cand*)&eT[0][0];            // [M_TILE][16]
#pragma unroll
    for (int r = 0; r < 8; ++r)
        red[(r0 + r) * 16 + tc] = Cand{best[r], bidx[r]};
    __syncthreads();

    if (tid < M_TILE) {
        const int row = tid;
        Cand bc = red[row * 16 + 0];
#pragma unroll
        for (int j = 1; j < 16; ++j) {
            Cand c = red[row * 16 + j];
            if (c.v > bc.v || (c.v == bc.v && c.i < bc.i)) bc = c;
        }
        out[rowBase + row] = (float)bc.i;
    }
}

// ---------------------------------------------------------------------------
// Harness entry
// ---------------------------------------------------------------------------
extern "C" void kernel_launch(void* const* d_in, const int* in_sizes, int n_in,
                              void* d_out, int out_size) {
    const float* inp = (const float*)d_in[0];
    const float* cb  = (const float*)d_in[1];
    if (in_sizes[0] == NUM_CODES * DIM && in_sizes[1] != NUM_CODES * DIM) {
        const float* tmp = inp; inp = cb; cb = tmp;
    }
    float* out = (float*)d_out;

    vq_prep_kernel<<<NUM_CODES / 256, 256>>>(cb);
    vq_search_kernel<<<N_ROWS / M_TILE, THREADS>>>(inp, out);
}